// round 14
// baseline (speedup 1.0000x reference)
#include <cuda_runtime.h>
#include <math_constants.h>

#define MAXB  256
#define LUTN  1024
#define TPB   1024
#define GRID  148          // one CTA per SM: single wave for K1 and K2
#define INF_BITS 0x7F800000u

// Persistent scratch (__device__ globals; no allocations allowed).
__device__ unsigned       g_tmax_bits = 0u; // idempotent across replays (never reset)
__device__ unsigned       g_done = 0u;      // reset by K1 block 0 each launch
__device__ float          g_bins_sorted[MAXB];
__device__ unsigned short g_lut[LUTN];      // k0 = count(bins < g/LUTN)
__device__ unsigned       g_cand_below[MAXB];
__device__ unsigned       g_cand_above[MAXB];
__device__ double         g_part[GRID];

// ---------------------------------------------------------------------------
// K1 (primary, 148x1024): block 0 -> bin prep + state reset (+ target tail);
// blocks 1..147 -> target max (float4, <=1 per thread).
// ---------------------------------------------------------------------------
__global__ __launch_bounds__(TPB)
void k1_prep_tmax(const float* __restrict__ bins, int nb,
                  const float* __restrict__ tgt, int n) {
    const int tid = threadIdx.x;
    __shared__ float red[TPB / 32];

    if (blockIdx.x == 0) {
        __shared__ float fv[MAXB];
        __shared__ float ss[MAXB];

        const int n4 = n >> 2;
        const int tailn = n - (n4 << 2);
        float m = 0.0f;
        if (tid < tailn) {                       // tail targets -> tmax
            float v = tgt[(n4 << 2) + tid];
            m = fmaxf(m, isfinite(v) ? v : 0.f);
        }

        float bm = -CUDART_INF_F;
        if (tid < nb) {
            float b = bins[tid];
            fv[tid] = b;
            bm = b;
        }
        for (int o = 16; o; o >>= 1) bm = fmaxf(bm, __shfl_xor_sync(0xffffffffu, bm, o));
        if ((tid & 31) == 0) red[tid >> 5] = bm;
        __syncthreads();
        float m0 = -CUDART_INF_F;
        #pragma unroll
        for (int i = 0; i < TPB / 32; i++) m0 = fmaxf(m0, red[i]);
        const float inv_bm = 1.0f / m0;
        if (tid < nb) fv[tid] *= inv_bm;
        __syncthreads();

        // rank sort (nb<=256; broadcast LDS reads)
        if (tid < nb) {
            float val = fv[tid];
            int rank = 0;
            #pragma unroll 8
            for (int j = 0; j < nb; j++) {
                float u = fv[j];
                rank += (u < val) || (u == val && j < tid);
            }
            ss[rank] = val;
        }
        __syncthreads();

        if (tid < nb) {
            g_bins_sorted[tid] = ss[tid];
            g_cand_below[tid]  = INF_BITS;
            g_cand_above[tid]  = INF_BITS;
        }
        // thin LUT: k0 = count(sorted bins < g/LUTN); pow2 edges exact floats
        {
            float edge = (float)tid * (1.0f / LUTN);   // TPB == LUTN
            int lo = 0, hi = nb;
            while (lo < hi) {
                int mid = (lo + hi) >> 1;
                if (ss[mid] < edge) lo = mid + 1; else hi = mid;
            }
            g_lut[tid] = (unsigned short)lo;
        }

        for (int o = 16; o; o >>= 1) m = fmaxf(m, __shfl_xor_sync(0xffffffffu, m, o));
        if ((tid & 31) == 0) red[tid >> 5] = m;
        __syncthreads();
        if (tid == 0) {
            float mm = red[0];
            #pragma unroll
            for (int i = 1; i < TPB / 32; i++) mm = fmaxf(mm, red[i]);
            atomicMax(&g_tmax_bits, __float_as_uint(mm));
            g_done = 0u;
        }
    } else {
        const int wb = blockIdx.x - 1;            // 0..146
        const int n4 = n >> 2;
        const float4* t4 = (const float4*)tgt;
        float m = 0.0f;
        // 147*1024 = 150528 >= n4 (76800): at most one float4 per thread
        for (int i = wb * TPB + tid; i < n4; i += (GRID - 1) * TPB) {
            float4 v = t4[i];
            m = fmaxf(m, isfinite(v.x) ? v.x : 0.f);
            m = fmaxf(m, isfinite(v.y) ? v.y : 0.f);
            m = fmaxf(m, isfinite(v.z) ? v.z : 0.f);
            m = fmaxf(m, isfinite(v.w) ? v.w : 0.f);
        }
        for (int o = 16; o; o >>= 1) m = fmaxf(m, __shfl_xor_sync(0xffffffffu, m, o));
        if ((tid & 31) == 0) red[tid >> 5] = m;
        __syncthreads();
        if (tid == 0) {
            float mm = red[0];
            #pragma unroll
            for (int i = 1; i < TPB / 32; i++) mm = fmaxf(mm, red[i]);
            atomicMax(&g_tmax_bits, __float_as_uint(mm)); // positive floats: bit order
        }
    }
    cudaTriggerProgrammaticLaunchCompletion();
}

// ---------------------------------------------------------------------------
// K2 (secondary, PDL, 148x1024): co-resident with K1 (1024+1024 <= 2048/SM).
// Preamble (overlaps K1): preload 2-3 elements/thread + shared init.
// After grid sync: LUT search (zero LDG), shared atomicMin staging, filtered
// global merge, last block runs min-scans + writes scalar.
// ---------------------------------------------------------------------------
__global__ __launch_bounds__(TPB)
void k2_main_final(const float* __restrict__ tgt, int n, int nb,
                   float* __restrict__ out) {
    __shared__ float          sb[MAXB];
    __shared__ unsigned short slut[LUTN];
    __shared__ unsigned       sbel[MAXB];
    __shared__ unsigned       sabv[MAXB];
    __shared__ float          red[TPB / 32];
    __shared__ bool           amLast;

    const int tid = threadIdx.x;
    const int bid = blockIdx.x;
    const int stride = GRID * TPB;     // 151552

    // ---- preamble: overlaps K1 (inputs + local smem only) ----
    const int i0 = bid * TPB + tid;
    const int i1 = i0 + stride;
    const int i2 = i1 + stride;
    float r0 = 0.f, r1 = 0.f, r2 = 0.f;
    const bool h0 = (i0 < n), h1 = (i1 < n), h2 = (i2 < n);
    if (h0) r0 = tgt[i0];
    if (h1) r1 = tgt[i1];
    if (h2) r2 = tgt[i2];
    if (tid < nb) { sbel[tid] = INF_BITS; sabv[tid] = INF_BITS; }
    if (tid == 0) amLast = false;

    // ---- wait for K1 (memory-coherent per PDL contract) ----
    cudaGridDependencySynchronize();

    if (tid < nb) sb[tid]  = g_bins_sorted[tid];
    slut[tid] = g_lut[tid];            // TPB == LUTN
    __syncthreads();

    const float inv = 1.0f / __uint_as_float(g_tmax_bits);
    float acc = 0.0f;

    auto proc = [&](float rawv) {
        float t = rawv * inv;
        int g = (int)(t * (float)LUTN);      // NaN cvt->0; clamp handles inf
        g = min(max(g, 0), LUTN - 1);
        int lo = slut[g];
        while (lo < nb && sb[lo] <= t) lo++; // avg ~0-1 steps
        float best = CUDART_INF_F;
        if (lo > 0) {
            float d = t - sb[lo - 1];
            best = d;
            atomicMin(&sabv[lo - 1], __float_as_uint(d));
        }
        if (lo < nb) {
            float d = sb[lo] - t;
            best = fminf(best, d);
            atomicMin(&sbel[lo], __float_as_uint(d));
        }
        if (isfinite(best)) acc += best * best;
    };

    if (h0) proc(r0);
    if (h1) proc(r1);
    if (h2) proc(r2);

    // dir2 block partial -> g_part[bid]
    for (int o = 16; o; o >>= 1) acc += __shfl_xor_sync(0xffffffffu, acc, o);
    if ((tid & 31) == 0) red[tid >> 5] = acc;
    __syncthreads();
    if (tid == 0) {
        double s = 0.0;
        #pragma unroll
        for (int i = 0; i < TPB / 32; i++) s += (double)red[i];
        g_part[bid] = s;
    }

    // merge candidate mins to global (filtered; spread addresses)
    if (tid < nb) {
        if (sbel[tid] != INF_BITS) atomicMin(&g_cand_below[tid], sbel[tid]);
        if (sabv[tid] != INF_BITS) atomicMin(&g_cand_above[tid], sabv[tid]);
    }

    __threadfence();
    __syncthreads();
    if (tid == 0) amLast = (atomicAdd(&g_done, 1u) == (unsigned)(GRID - 1));
    __syncthreads();
    if (!amLast) return;

    // d_above[j] = min_{k>=j}(cand_above[k]+b[k]) - b[j]  (suffix min)
    // d_below[j] = min_{k<=j}(cand_below[k]-b[k]) + b[j]  (prefix min)
    float* fA = (float*)sabv;
    float* fB = (float*)sbel;
    if (tid < nb) {
        float b  = sb[tid];
        float ca = __uint_as_float(*(volatile unsigned*)&g_cand_above[tid]);
        float cb = __uint_as_float(*(volatile unsigned*)&g_cand_below[tid]);
        fA[tid] = ca + b;
        fB[tid] = cb - b;
    }
    __syncthreads();
    for (int off = 1; off < nb; off <<= 1) {
        float a = CUDART_INF_F, bp = CUDART_INF_F;
        if (tid < nb) {
            if (tid + off < nb) a  = fA[tid + off];
            if (tid >= off)     bp = fB[tid - off];
        }
        __syncthreads();
        if (tid < nb) {
            fA[tid] = fminf(fA[tid], a);
            fB[tid] = fminf(fB[tid], bp);
        }
        __syncthreads();
    }

    double total = 0.0;
    if (tid < nb) {
        float nn = fminf(fA[tid] - sb[tid], fB[tid] + sb[tid]);
        if (isfinite(nn)) total = (double)nn * (double)nn;
    }
    if (tid < GRID) total += *(volatile double*)&g_part[tid];

    for (int o = 16; o; o >>= 1) total += __shfl_xor_sync(0xffffffffu, total, o);
    __shared__ double sd[TPB / 32];
    if ((tid & 31) == 0) sd[tid >> 5] = total;
    __syncthreads();
    if (tid == 0) {
        double s = 0.0;
        #pragma unroll
        for (int i = 0; i < TPB / 32; i++) s += sd[i];
        out[0] = (float)s;
    }
}

// ---------------------------------------------------------------------------
extern "C" void kernel_launch(void* const* d_in, const int* in_sizes, int n_in,
                              void* d_out, int out_size) {
    const float* tgt;
    const float* bins;
    int nT, nB;
    if (in_sizes[0] >= in_sizes[1]) {
        tgt = (const float*)d_in[0]; nT = in_sizes[0];
        bins = (const float*)d_in[1]; nB = in_sizes[1];
    } else {
        tgt = (const float*)d_in[1]; nT = in_sizes[1];
        bins = (const float*)d_in[0]; nB = in_sizes[0];
    }
    if (nB > MAXB) nB = MAXB;  // defensive; actual nB = 256
    // K2 covers n <= 3 * 148 * 1024 = 454656 (actual n = 307200).

    // primary
    k1_prep_tmax<<<GRID, TPB>>>(bins, nB, tgt, nT);

    // secondary with programmatic dependent launch (graph-capturable)
    cudaLaunchConfig_t cfg = {};
    cfg.gridDim  = dim3(GRID, 1, 1);
    cfg.blockDim = dim3(TPB, 1, 1);
    cfg.dynamicSmemBytes = 0;
    cfg.stream = 0;
    cudaLaunchAttribute attrs[1];
    attrs[0].id = cudaLaunchAttributeProgrammaticStreamSerialization;
    attrs[0].val.programmaticStreamSerializationAllowed = 1;
    cfg.attrs = attrs;
    cfg.numAttrs = 1;

    float* outp = (float*)d_out;
    cudaLaunchKernelEx(&cfg, k2_main_final, tgt, nT, nB, outp);
}

// round 15
// speedup vs baseline: 1.3049x; 1.3049x over previous
#include <cuda_runtime.h>
#include <math_constants.h>

#define MAXB 256
#define TPB  256
#define LUTN 1024
#define INF_BITS 0x7F800000u
#define MAXGRID 1100
#define NMAXSLOT 32

// Persistent scratch (__device__ globals; no allocations allowed).
__device__ unsigned       g_maxpart[NMAXSLOT]; // scattered tmax partials; idempotent
__device__ unsigned       g_bar1 = 0u;         // reset by last block at end of launch
__device__ unsigned       g_done = 0u;         // reset by block 0 in phase 1
__device__ float          g_bins_sorted[MAXB];
__device__ unsigned short g_lut[LUTN];         // k0 = count(bins < g/LUTN)
__device__ unsigned       g_cand_below[MAXB];  // re-INF'd by block 0 in phase 1
__device__ unsigned       g_cand_above[MAXB];
__device__ double         g_part[MAXGRID];

__global__ __launch_bounds__(TPB)
void k_all(const float* __restrict__ bins, int nb,
           const float* __restrict__ tgt, int n,
           float* __restrict__ out) {
    __shared__ float          sb[MAXB];
    __shared__ unsigned       sbel[MAXB];
    __shared__ unsigned       sabv[MAXB];
    __shared__ unsigned short slut[LUTN];
    __shared__ float          red[TPB / 32];
    __shared__ float          sT;
    __shared__ bool           amLast;

    const int tid  = threadIdx.x;
    const int bid  = blockIdx.x;
    const int grid = gridDim.x;
    const int n4   = n >> 2;
    const int tailn = n - (n4 << 2);
    const bool reg_path = (grid * TPB >= n4);  // every thread owns <=1 float4

    // ---------------- Phase 1: target max (+ block 0: bin prep) -----------
    float4 v   = make_float4(0.f, 0.f, 0.f, 0.f);
    bool   have = false;
    float  tailv = 0.f;
    bool   havetail = false;
    float  m = 0.0f;

    if (reg_path) {
        int idx = bid * TPB + tid;
        if (idx < n4) { v = ((const float4*)tgt)[idx]; have = true; }
        if (have) {
            m = fmaxf(m, isfinite(v.x) ? v.x : 0.f);
            m = fmaxf(m, isfinite(v.y) ? v.y : 0.f);
            m = fmaxf(m, isfinite(v.z) ? v.z : 0.f);
            m = fmaxf(m, isfinite(v.w) ? v.w : 0.f);
        }
    } else {
        int stride = grid * TPB;
        const float4* t4 = (const float4*)tgt;
        for (int i = bid * TPB + tid; i < n4; i += stride) {
            float4 u = t4[i];
            m = fmaxf(m, isfinite(u.x) ? u.x : 0.f);
            m = fmaxf(m, isfinite(u.y) ? u.y : 0.f);
            m = fmaxf(m, isfinite(u.z) ? u.z : 0.f);
            m = fmaxf(m, isfinite(u.w) ? u.w : 0.f);
        }
    }
    if (bid == 0 && tid < tailn) {
        tailv = tgt[(n4 << 2) + tid];
        havetail = true;
        m = fmaxf(m, isfinite(tailv) ? tailv : 0.f);
    }

    for (int o = 16; o; o >>= 1) m = fmaxf(m, __shfl_xor_sync(0xffffffffu, m, o));
    if ((tid & 31) == 0) red[tid >> 5] = m;
    __syncthreads();
    if (tid == 0) {
        float mm = red[0];
        #pragma unroll
        for (int i = 1; i < TPB / 32; i++) mm = fmaxf(mm, red[i]);
        atomicMax(&g_maxpart[bid & (NMAXSLOT - 1)], __float_as_uint(mm));
    }

    if (bid == 0) {
        // Bin prep: max, normalize, rank-sort into sb, publish + LUT.
        float* fraw = (float*)sbel;   // scratch
        __syncthreads();
        float bm = -CUDART_INF_F;
        for (int i = tid; i < nb; i += TPB) {
            float b = bins[i];
            fraw[i] = b;
            bm = fmaxf(bm, b);
        }
        for (int o = 16; o; o >>= 1) bm = fmaxf(bm, __shfl_xor_sync(0xffffffffu, bm, o));
        if ((tid & 31) == 0) red[tid >> 5] = bm;
        __syncthreads();
        float inv_bm = 1.0f / fmaxf(fmaxf(fmaxf(red[0], red[1]),
                                          fmaxf(red[2], red[3])),
                                    fmaxf(fmaxf(red[4], red[5]),
                                          fmaxf(red[6], red[7])));
        for (int i = tid; i < nb; i += TPB) fraw[i] *= inv_bm;
        __syncthreads();
        for (int i = tid; i < nb; i += TPB) {
            float val = fraw[i];
            int rank = 0;
            for (int j = 0; j < nb; j++) {
                float u = fraw[j];
                rank += (u < val) || (u == val && j < i);
            }
            sb[rank] = val;
        }
        __syncthreads();
        for (int i = tid; i < nb; i += TPB) {
            g_bins_sorted[i] = sb[i];
            g_cand_below[i]  = INF_BITS;
            g_cand_above[i]  = INF_BITS;
        }
        // thin LUT: k0 = count(sorted bins < g/LUTN); pow2 edges exact floats
        for (int g = tid; g < LUTN; g += TPB) {
            float edge = (float)g * (1.0f / LUTN);
            int lo = 0, hi = nb;
            while (lo < hi) {
                int mid = (lo + hi) >> 1;
                if (sb[mid] < edge) lo = mid + 1; else hi = mid;
            }
            g_lut[g] = (unsigned short)lo;
        }
        if (tid == 0) g_done = 0u;
    }

    // ---------------- Grid barrier ----------------------------------------
    if (tid == 0) {
        __threadfence();
        atomicAdd(&g_bar1, 1u);
        while (*(volatile unsigned*)&g_bar1 < (unsigned)grid) __nanosleep(64);
        __threadfence();
    }
    __syncthreads();

    // ---------------- Phase 2: main pass ----------------------------------
    if (bid != 0) {
        for (int i = tid; i < nb; i += TPB)
            sb[i] = *((volatile float*)&g_bins_sorted[i]);
    }
    for (int i = tid; i < nb; i += TPB) { sbel[i] = INF_BITS; sabv[i] = INF_BITS; }
    for (int i = tid; i < LUTN; i += TPB)
        slut[i] = *((volatile unsigned short*)&g_lut[i]);
    // reduce the 32 scattered max partials (volatile: bypass L1)
    if (tid < 32) {
        float mv = __uint_as_float(*(volatile unsigned*)&g_maxpart[tid]);
        for (int o = 16; o; o >>= 1)
            mv = fmaxf(mv, __shfl_xor_sync(0xffffffffu, mv, o));
        if (tid == 0) sT = mv;
    }
    __syncthreads();

    const float inv = 1.0f / sT;
    float acc = 0.0f;

    auto proc = [&](float raw) {
        float t = raw * inv;
        // LUT start + short walk (NaN cvt->0, clamp handles inf; NaN/inf flow
        // safely: distances become NaN/inf, filtered below / skipped by isfinite)
        int g = (int)(t * (float)LUTN);
        g = min(max(g, 0), LUTN - 1);
        int lo = slut[g];
        while (lo < nb && sb[lo] <= t) lo++;   // avg ~0-1 steps
        float best = CUDART_INF_F;
        if (lo > 0) {
            float d = t - sb[lo - 1];
            best = d;
            // READ-FILTERED shared atomic: value only decreases, so a stale
            // (higher) read can only cause a redundant atomic, never a miss.
            unsigned db = __float_as_uint(d);
            if (db < sabv[lo - 1]) atomicMin(&sabv[lo - 1], db);
        }
        if (lo < nb) {
            float d = sb[lo] - t;
            best = fminf(best, d);
            unsigned db = __float_as_uint(d);
            if (db < sbel[lo]) atomicMin(&sbel[lo], db);
        }
        if (isfinite(best)) acc += best * best;
    };

    if (reg_path) {
        if (have) { proc(v.x); proc(v.y); proc(v.z); proc(v.w); }
    } else {
        int stride = grid * TPB;
        const float4* t4 = (const float4*)tgt;
        for (int i = bid * TPB + tid; i < n4; i += stride) {
            float4 u = t4[i];
            proc(u.x); proc(u.y); proc(u.z); proc(u.w);
        }
    }
    if (havetail) proc(tailv);

    // dir2 block partial -> g_part[bid]
    for (int o = 16; o; o >>= 1) acc += __shfl_xor_sync(0xffffffffu, acc, o);
    if ((tid & 31) == 0) red[tid >> 5] = acc;
    __syncthreads();
    if (tid == 0) {
        double s = 0.0;
        #pragma unroll
        for (int i = 0; i < TPB / 32; i++) s += (double)red[i];
        g_part[bid] = s;
    }
    __syncthreads();   // all shared atomics done before merge reads sbel/sabv

    // merge candidate mins to global (read-filtered; spread addresses)
    for (int i = tid; i < nb; i += TPB) {
        unsigned b = sbel[i];
        if (b != INF_BITS && b < *(volatile unsigned*)&g_cand_below[i])
            atomicMin(&g_cand_below[i], b);
        unsigned a = sabv[i];
        if (a != INF_BITS && a < *(volatile unsigned*)&g_cand_above[i])
            atomicMin(&g_cand_above[i], a);
    }

    // ---------------- Last block: final scan + output ----------------------
    __threadfence();
    __syncthreads();
    if (tid == 0) amLast = (atomicAdd(&g_done, 1u) == (unsigned)(grid - 1));
    __syncthreads();
    if (!amLast) return;

    // d_above[j] = min_{k>=j}(cand_above[k]+b[k]) - b[j]  (suffix min)
    // d_below[j] = min_{k<=j}(cand_below[k]-b[k]) + b[j]  (prefix min)
    float* fA = (float*)sabv;
    float* fB = (float*)sbel;
    if (tid < nb) {
        float b  = sb[tid];
        float ca = __uint_as_float(*((volatile unsigned*)&g_cand_above[tid]));
        float cb = __uint_as_float(*((volatile unsigned*)&g_cand_below[tid]));
        fA[tid] = ca + b;
        fB[tid] = cb - b;
    }
    __syncthreads();
    for (int off = 1; off < nb; off <<= 1) {
        float a = CUDART_INF_F, bp = CUDART_INF_F;
        if (tid < nb) {
            if (tid + off < nb) a  = fA[tid + off];
            if (tid >= off)     bp = fB[tid - off];
        }
        __syncthreads();
        if (tid < nb) {
            fA[tid] = fminf(fA[tid], a);
            fB[tid] = fminf(fB[tid], bp);
        }
        __syncthreads();
    }

    double total = 0.0;
    if (tid < nb) {
        float nn = fminf(fA[tid] - sb[tid], fB[tid] + sb[tid]);
        if (isfinite(nn)) total = (double)nn * (double)nn;
    }
    for (int i = tid; i < grid; i += TPB) total += *(volatile double*)&g_part[i];

    for (int o = 16; o; o >>= 1) total += __shfl_xor_sync(0xffffffffu, total, o);
    __shared__ double sd[TPB / 32];
    if ((tid & 31) == 0) sd[tid >> 5] = total;
    __syncthreads();
    if (tid == 0) {
        double s = 0.0;
        #pragma unroll
        for (int i = 0; i < TPB / 32; i++) s += sd[i];
        out[0] = (float)s;
        g_bar1 = 0u;   // reset for next replay (everyone is past the spin)
    }
}

// ---------------------------------------------------------------------------
extern "C" void kernel_launch(void* const* d_in, const int* in_sizes, int n_in,
                              void* d_out, int out_size) {
    const float* tgt;
    const float* bins;
    int nT, nB;
    if (in_sizes[0] >= in_sizes[1]) {
        tgt = (const float*)d_in[0]; nT = in_sizes[0];
        bins = (const float*)d_in[1]; nB = in_sizes[1];
    } else {
        tgt = (const float*)d_in[1]; nT = in_sizes[1];
        bins = (const float*)d_in[0]; nB = in_sizes[0];
    }
    if (nB > MAXB) nB = MAXB;  // defensive; actual nB = 256

    int n4 = nT >> 2;
    int blocks = (n4 + TPB - 1) / TPB;   // one float4 per thread
    if (blocks < 1) blocks = 1;
    if (blocks > MAXGRID) blocks = MAXGRID;  // falls back to strided loop

    k_all<<<blocks, TPB>>>(bins, nB, tgt, nT, (float*)d_out);
}

// round 16
// speedup vs baseline: 1.4459x; 1.1081x over previous
#include <cuda_runtime.h>
#include <math_constants.h>

#define MAXB 256
#define TPB  256
#define LUTN 256
#define INF_BITS 0x7F800000u
#define MAXGRID 1100
#define NMAXSLOT 32

// Persistent scratch (__device__ globals; no allocations allowed).
__device__ unsigned g_maxpart[NMAXSLOT]; // scattered tmax partials; idempotent
__device__ unsigned g_bar1 = 0u;         // reset by last block at end of launch
__device__ unsigned g_done = 0u;         // reset by block 0 in phase 1
__device__ float    g_bins_sorted[MAXB];
__device__ float4   g_lut4[LUTN];        // {lo_val, hi_val, k0_bits, 0} per bucket
__device__ unsigned g_cand_below[MAXB];  // re-INF'd by block 0 in phase 1
__device__ unsigned g_cand_above[MAXB];
__device__ double   g_part[MAXGRID];

__global__ __launch_bounds__(TPB)
void k_all(const float* __restrict__ bins, int nb,
           const float* __restrict__ tgt, int n,
           float* __restrict__ out) {
    __shared__ float    sb[MAXB];
    __shared__ unsigned sbel[MAXB];
    __shared__ unsigned sabv[MAXB];
    __shared__ float4   slut4[LUTN];     // 4KB fat LUT
    __shared__ float    red[TPB / 32];
    __shared__ float    sT;
    __shared__ bool     amLast;

    const int tid  = threadIdx.x;
    const int bid  = blockIdx.x;
    const int grid = gridDim.x;
    const int n4   = n >> 2;
    const int tailn = n - (n4 << 2);
    const bool reg_path = (grid * TPB >= n4);  // every thread owns <=1 float4

    // ---------------- Phase 1: target max (+ block 0: bin prep) -----------
    float4 v   = make_float4(0.f, 0.f, 0.f, 0.f);
    bool   have = false;
    float  tailv = 0.f;
    bool   havetail = false;
    float  m = 0.0f;

    if (reg_path) {
        int idx = bid * TPB + tid;
        if (idx < n4) { v = ((const float4*)tgt)[idx]; have = true; }
        if (have) {
            m = fmaxf(m, isfinite(v.x) ? v.x : 0.f);
            m = fmaxf(m, isfinite(v.y) ? v.y : 0.f);
            m = fmaxf(m, isfinite(v.z) ? v.z : 0.f);
            m = fmaxf(m, isfinite(v.w) ? v.w : 0.f);
        }
    } else {
        int stride = grid * TPB;
        const float4* t4 = (const float4*)tgt;
        for (int i = bid * TPB + tid; i < n4; i += stride) {
            float4 u = t4[i];
            m = fmaxf(m, isfinite(u.x) ? u.x : 0.f);
            m = fmaxf(m, isfinite(u.y) ? u.y : 0.f);
            m = fmaxf(m, isfinite(u.z) ? u.z : 0.f);
            m = fmaxf(m, isfinite(u.w) ? u.w : 0.f);
        }
    }
    if (bid == 0 && tid < tailn) {
        tailv = tgt[(n4 << 2) + tid];
        havetail = true;
        m = fmaxf(m, isfinite(tailv) ? tailv : 0.f);
    }

    for (int o = 16; o; o >>= 1) m = fmaxf(m, __shfl_xor_sync(0xffffffffu, m, o));
    if ((tid & 31) == 0) red[tid >> 5] = m;
    __syncthreads();
    if (tid == 0) {
        float mm = red[0];
        #pragma unroll
        for (int i = 1; i < TPB / 32; i++) mm = fmaxf(mm, red[i]);
        atomicMax(&g_maxpart[bid & (NMAXSLOT - 1)], __float_as_uint(mm));
    }

    if (bid == 0) {
        // Bin prep: max, normalize, rank-sort into sb, publish + fat LUT.
        float* fraw = (float*)sbel;   // scratch
        __syncthreads();
        float bm = -CUDART_INF_F;
        for (int i = tid; i < nb; i += TPB) {
            float b = bins[i];
            fraw[i] = b;
            bm = fmaxf(bm, b);
        }
        for (int o = 16; o; o >>= 1) bm = fmaxf(bm, __shfl_xor_sync(0xffffffffu, bm, o));
        if ((tid & 31) == 0) red[tid >> 5] = bm;
        __syncthreads();
        float inv_bm = 1.0f / fmaxf(fmaxf(fmaxf(red[0], red[1]),
                                          fmaxf(red[2], red[3])),
                                    fmaxf(fmaxf(red[4], red[5]),
                                          fmaxf(red[6], red[7])));
        for (int i = tid; i < nb; i += TPB) fraw[i] *= inv_bm;
        __syncthreads();
        for (int i = tid; i < nb; i += TPB) {
            float val = fraw[i];
            int rank = 0;
            for (int j = 0; j < nb; j++) {
                float u = fraw[j];
                rank += (u < val) || (u == val && j < i);
            }
            sb[rank] = val;
        }
        __syncthreads();
        for (int i = tid; i < nb; i += TPB) {
            g_bins_sorted[i] = sb[i];
            g_cand_below[i]  = INF_BITS;
            g_cand_above[i]  = INF_BITS;
        }
        // fat LUT (one entry per thread): k0 = count(bins <= g/LUTN),
        // lo_val = sb[k0-1] (or -inf), hi_val = sb[k0] (or +inf).
        // Bucket edges g/LUTN are exact (pow2), so t in bucket g => t >= edge.
        {
            float edge = (float)tid * (1.0f / LUTN);
            int lo = 0, hi = nb;
            while (lo < hi) {
                int mid = (lo + hi) >> 1;
                if (sb[mid] <= edge) lo = mid + 1; else hi = mid;
            }
            float lv = (lo > 0)  ? sb[lo - 1] : -CUDART_INF_F;
            float hv = (lo < nb) ? sb[lo]     :  CUDART_INF_F;
            g_lut4[tid] = make_float4(lv, hv, __int_as_float(lo), 0.f);
        }
        if (tid == 0) g_done = 0u;
    }

    // ---------------- Grid barrier ----------------------------------------
    if (tid == 0) {
        __threadfence();
        atomicAdd(&g_bar1, 1u);
        while (*(volatile unsigned*)&g_bar1 < (unsigned)grid) __nanosleep(64);
        __threadfence();
    }
    __syncthreads();

    // ---------------- Phase 2: main pass ----------------------------------
    if (bid != 0) {
        for (int i = tid; i < nb; i += TPB)
            sb[i] = *((volatile float*)&g_bins_sorted[i]);
    }
    for (int i = tid; i < nb; i += TPB) { sbel[i] = INF_BITS; sabv[i] = INF_BITS; }
    // First touch of g_lut4 on this SM after the barrier -> L2-correct data.
    slut4[tid] = g_lut4[tid];            // TPB == LUTN
    // reduce the 32 scattered max partials (volatile: bypass L1)
    if (tid < 32) {
        float mv = __uint_as_float(*(volatile unsigned*)&g_maxpart[tid]);
        for (int o = 16; o; o >>= 1)
            mv = fmaxf(mv, __shfl_xor_sync(0xffffffffu, mv, o));
        if (tid == 0) sT = mv;
    }
    __syncthreads();

    const float inv = 1.0f / sT;
    float acc = 0.0f;

    auto proc = [&](float raw) {
        float t = raw * inv;
        int g = (int)(t * (float)LUTN);      // NaN cvt->0; clamp handles inf
        g = min(max(g, 0), LUTN - 1);
        float4 e = slut4[g];                 // one LDS.128: {lv, hv, k0}
        int   lo = __float_as_int(e.z);
        float lv = e.x, hv = e.y;
        if (t >= hv && lo < nb) {            // slow path (~37%): bin(s) in (edge,t]
            lo++;                             // sb[k0] <= t, so advance at least 1
            while (lo < nb && sb[lo] <= t) lo++;
            lv = sb[lo - 1];
            hv = (lo < nb) ? sb[lo] : CUDART_INF_F;
        }
        float best = CUDART_INF_F;
        if (lo > 0) {
            float d = t - lv;
            best = d;
            atomicMin(&sabv[lo - 1], __float_as_uint(d));
        }
        if (lo < nb) {
            float d = hv - t;
            best = fminf(best, d);
            atomicMin(&sbel[lo], __float_as_uint(d));
        }
        if (isfinite(best)) acc += best * best;
    };

    if (reg_path) {
        if (have) { proc(v.x); proc(v.y); proc(v.z); proc(v.w); }
    } else {
        int stride = grid * TPB;
        const float4* t4 = (const float4*)tgt;
        for (int i = bid * TPB + tid; i < n4; i += stride) {
            float4 u = t4[i];
            proc(u.x); proc(u.y); proc(u.z); proc(u.w);
        }
    }
    if (havetail) proc(tailv);

    // dir2 block partial -> g_part[bid]
    for (int o = 16; o; o >>= 1) acc += __shfl_xor_sync(0xffffffffu, acc, o);
    if ((tid & 31) == 0) red[tid >> 5] = acc;
    __syncthreads();
    if (tid == 0) {
        double s = 0.0;
        #pragma unroll
        for (int i = 0; i < TPB / 32; i++) s += (double)red[i];
        g_part[bid] = s;
    }
    __syncthreads();   // all shared atomics done before merge reads sbel/sabv

    // merge candidate mins to global (read-filtered; spread addresses)
    for (int i = tid; i < nb; i += TPB) {
        unsigned b = sbel[i];
        if (b != INF_BITS && b < *(volatile unsigned*)&g_cand_below[i])
            atomicMin(&g_cand_below[i], b);
        unsigned a = sabv[i];
        if (a != INF_BITS && a < *(volatile unsigned*)&g_cand_above[i])
            atomicMin(&g_cand_above[i], a);
    }

    // ---------------- Last block: final scan + output ----------------------
    __threadfence();
    __syncthreads();
    if (tid == 0) amLast = (atomicAdd(&g_done, 1u) == (unsigned)(grid - 1));
    __syncthreads();
    if (!amLast) return;

    // d_above[j] = min_{k>=j}(cand_above[k]+b[k]) - b[j]  (suffix min)
    // d_below[j] = min_{k<=j}(cand_below[k]-b[k]) + b[j]  (prefix min)
    float* fA = (float*)sabv;
    float* fB = (float*)sbel;
    if (tid < nb) {
        float b  = sb[tid];
        float ca = __uint_as_float(*((volatile unsigned*)&g_cand_above[tid]));
        float cb = __uint_as_float(*((volatile unsigned*)&g_cand_below[tid]));
        fA[tid] = ca + b;
        fB[tid] = cb - b;
    }
    __syncthreads();
    for (int off = 1; off < nb; off <<= 1) {
        float a = CUDART_INF_F, bp = CUDART_INF_F;
        if (tid < nb) {
            if (tid + off < nb) a  = fA[tid + off];
            if (tid >= off)     bp = fB[tid - off];
        }
        __syncthreads();
        if (tid < nb) {
            fA[tid] = fminf(fA[tid], a);
            fB[tid] = fminf(fB[tid], bp);
        }
        __syncthreads();
    }

    double total = 0.0;
    if (tid < nb) {
        float nn = fminf(fA[tid] - sb[tid], fB[tid] + sb[tid]);
        if (isfinite(nn)) total = (double)nn * (double)nn;
    }
    for (int i = tid; i < grid; i += TPB) total += *(volatile double*)&g_part[i];

    for (int o = 16; o; o >>= 1) total += __shfl_xor_sync(0xffffffffu, total, o);
    __shared__ double sd[TPB / 32];
    if ((tid & 31) == 0) sd[tid >> 5] = total;
    __syncthreads();
    if (tid == 0) {
        double s = 0.0;
        #pragma unroll
        for (int i = 0; i < TPB / 32; i++) s += sd[i];
        out[0] = (float)s;
        g_bar1 = 0u;   // reset for next replay (everyone is past the spin)
    }
}

// ---------------------------------------------------------------------------
extern "C" void kernel_launch(void* const* d_in, const int* in_sizes, int n_in,
                              void* d_out, int out_size) {
    const float* tgt;
    const float* bins;
    int nT, nB;
    if (in_sizes[0] >= in_sizes[1]) {
        tgt = (const float*)d_in[0]; nT = in_sizes[0];
        bins = (const float*)d_in[1]; nB = in_sizes[1];
    } else {
        tgt = (const float*)d_in[1]; nT = in_sizes[1];
        bins = (const float*)d_in[0]; nB = in_sizes[0];
    }
    if (nB > MAXB) nB = MAXB;  // defensive; actual nB = 256

    int n4 = nT >> 2;
    int blocks = (n4 + TPB - 1) / TPB;   // one float4 per thread
    if (blocks < 1) blocks = 1;
    if (blocks > MAXGRID) blocks = MAXGRID;  // falls back to strided loop

    k_all<<<blocks, TPB>>>(bins, nB, tgt, nT, (float*)d_out);
}